// round 1
// baseline (speedup 1.0000x reference)
#include <cuda_runtime.h>

#define NN 20000
#define NE 320000
#define IF 16
#define OF 16
#define EDIM 16
#define EHID 64
#define BN_EPS 1e-5f

// scratch (allocation-free rule: __device__ globals)
__device__ float g_neigh[NN * OF];
__device__ float g_y[NN * OF];
__device__ float g_stats[2 * OF];

typedef unsigned long long u64;

__device__ __forceinline__ u64 pk2(float a, float b) {
    u64 r;
    asm("mov.b64 %0, {%1, %2};" : "=l"(r) : "f"(a), "f"(b));
    return r;
}
__device__ __forceinline__ void upk2(u64 v, float &a, float &b) {
    asm("mov.b64 {%0, %1}, %2;" : "=f"(a), "=f"(b) : "l"(v));
}
// packed fp32x2 FMA (sm_100+ only; ptxas never auto-fuses this)
__device__ __forceinline__ void fma2(u64 &d, u64 a, u64 b) {
    asm("fma.rn.f32x2 %0, %1, %2, %0;" : "+l"(d) : "l"(a), "l"(b));
}

// ---------------------------------------------------------------------------
__global__ void k_zero() {
    int i = blockIdx.x * blockDim.x + threadIdx.x;
    if (i < NN * OF) g_neigh[i] = 0.0f;
    if (i < 2 * OF) g_stats[i] = 0.0f;
}

// ---------------------------------------------------------------------------
// y = h_self @ W_self  -> g_y ; accumulate per-column sum / sumsq -> g_stats
__global__ __launch_bounds__(256) void k_self(const float* __restrict__ hs,
                                              const float* __restrict__ Ws) {
    __shared__ float sW[IF * OF];
    sW[threadIdx.x] = Ws[threadIdx.x];
    __syncthreads();

    int n = blockIdx.x * 256 + threadIdx.x;
    float yv[OF];
#pragma unroll
    for (int o = 0; o < OF; o++) yv[o] = 0.0f;

    if (n < NN) {
        float h[IF];
        const float4* hp = (const float4*)(hs + (size_t)n * IF);
        float4 a = hp[0], b = hp[1], c = hp[2], d = hp[3];
        h[0]=a.x; h[1]=a.y; h[2]=a.z; h[3]=a.w;
        h[4]=b.x; h[5]=b.y; h[6]=b.z; h[7]=b.w;
        h[8]=c.x; h[9]=c.y; h[10]=c.z; h[11]=c.w;
        h[12]=d.x; h[13]=d.y; h[14]=d.z; h[15]=d.w;
#pragma unroll
        for (int o = 0; o < OF; o++) {
            float acc = 0.0f;
#pragma unroll
            for (int i = 0; i < IF; i++) acc = fmaf(h[i], sW[i * OF + o], acc);
            yv[o] = acc;
        }
        float* yp = g_y + (size_t)n * OF;
#pragma unroll
        for (int o = 0; o < OF; o++) yp[o] = yv[o];
    }

    // warp reduction of sums & sum-of-squares per column
    float s1[OF], s2[OF];
#pragma unroll
    for (int o = 0; o < OF; o++) { s1[o] = yv[o]; s2[o] = yv[o] * yv[o]; }
#pragma unroll
    for (int off = 16; off > 0; off >>= 1) {
#pragma unroll
        for (int o = 0; o < OF; o++) {
            s1[o] += __shfl_down_sync(0xffffffffu, s1[o], off);
            s2[o] += __shfl_down_sync(0xffffffffu, s2[o], off);
        }
    }
    if ((threadIdx.x & 31) == 0) {
#pragma unroll
        for (int o = 0; o < OF; o++) {
            atomicAdd(&g_stats[o], s1[o]);
            atomicAdd(&g_stats[OF + o], s2[o]);
        }
    }
}

// ---------------------------------------------------------------------------
// Fused edge kernel: eh = relu(ef@We1+be1); msg = x^T (eh@We2+be2 reshaped);
// atomic scatter to g_neigh[dst]. One thread per edge; weights in SMEM.
#define SMEM_FLOATS (1024 + 64 + 256 + 16384)

__global__ __launch_bounds__(256) void k_edge(
    const float* __restrict__ ef_g, const float* __restrict__ hn,
    const int* __restrict__ src, const int* __restrict__ dst,
    const float* __restrict__ We1, const float* __restrict__ be1,
    const float* __restrict__ We2, const float* __restrict__ be2) {
    extern __shared__ float sm[];
    float* sWe1 = sm;          // [16][64]
    float* sbe1 = sm + 1024;   // [64]
    float* sbe2 = sm + 1088;   // [256]
    float* sWe2 = sm + 1344;   // [64][256]

    for (int t = threadIdx.x; t < 1024 / 4; t += 256)
        ((float4*)sWe1)[t] = ((const float4*)We1)[t];
    if (threadIdx.x < 64) sbe1[threadIdx.x] = be1[threadIdx.x];
    sbe2[threadIdx.x] = be2[threadIdx.x];
    for (int t = threadIdx.x; t < 16384 / 4; t += 256)
        ((float4*)sWe2)[t] = ((const float4*)We2)[t];
    __syncthreads();

    int e = blockIdx.x * 256 + threadIdx.x;
    if (e >= NE) return;

    // gather src features + edge features (vectorized)
    float x[16], ef[16];
    {
        const float4* xp = (const float4*)(hn + (size_t)src[e] * IF);
        float4 a = xp[0], b = xp[1], c = xp[2], d = xp[3];
        x[0]=a.x; x[1]=a.y; x[2]=a.z; x[3]=a.w;
        x[4]=b.x; x[5]=b.y; x[6]=b.z; x[7]=b.w;
        x[8]=c.x; x[9]=c.y; x[10]=c.z; x[11]=c.w;
        x[12]=d.x; x[13]=d.y; x[14]=d.z; x[15]=d.w;
        const float4* ep = (const float4*)(ef_g + (size_t)e * EDIM);
        a = ep[0]; b = ep[1]; c = ep[2]; d = ep[3];
        ef[0]=a.x; ef[1]=a.y; ef[2]=a.z; ef[3]=a.w;
        ef[4]=b.x; ef[5]=b.y; ef[6]=b.z; ef[7]=b.w;
        ef[8]=c.x; ef[9]=c.y; ef[10]=c.z; ef[11]=c.w;
        ef[12]=d.x; ef[13]=d.y; ef[14]=d.z; ef[15]=d.w;
    }

    u64 ef2[16];
#pragma unroll
    for (int i = 0; i < 16; i++) ef2[i] = pk2(ef[i], ef[i]);

    // msg init: sum_i x_i * be2[i*16 + o]   (o packed in pairs)
    u64 msg[8];
#pragma unroll
    for (int o2 = 0; o2 < 8; o2++) msg[o2] = pk2(0.0f, 0.0f);
#pragma unroll
    for (int i = 0; i < 16; i++) {
        u64 xp2 = pk2(x[i], x[i]);
        const float2* bp = (const float2*)(sbe2 + i * 16);
#pragma unroll
        for (int o2 = 0; o2 < 8; o2++) {
            float2 b = bp[o2];
            fma2(msg[o2], xp2, pk2(b.x, b.y));
        }
    }

    // main: for each h-pair, compute eh (packed), then
    // msg[o] += (eh_h * x_i) * We2[h, 16i+o]
#pragma unroll 1
    for (int h2 = 0; h2 < 32; ++h2) {
        float2 bb = ((const float2*)sbe1)[h2];
        u64 acc = pk2(bb.x, bb.y);
#pragma unroll
        for (int i = 0; i < 16; i++) {
            float2 w = ((const float2*)(sWe1 + i * 64))[h2];
            fma2(acc, ef2[i], pk2(w.x, w.y));
        }
        float e0, e1;
        upk2(acc, e0, e1);
        e0 = fmaxf(e0, 0.0f);
        e1 = fmaxf(e1, 0.0f);

        const float4* w0 = (const float4*)(sWe2 + (h2 * 2) * 256);
        const float4* w1 = w0 + 64;  // next h row
#pragma unroll
        for (int i = 0; i < 16; i++) {
            float a0 = e0 * x[i];
            float a1 = e1 * x[i];
            u64 a0p = pk2(a0, a0);
            u64 a1p = pk2(a1, a1);
#pragma unroll
            for (int j = 0; j < 4; j++) {
                float4 v = w0[i * 4 + j];
                fma2(msg[2 * j],     a0p, pk2(v.x, v.y));
                fma2(msg[2 * j + 1], a0p, pk2(v.z, v.w));
            }
#pragma unroll
            for (int j = 0; j < 4; j++) {
                float4 v = w1[i * 4 + j];
                fma2(msg[2 * j],     a1p, pk2(v.x, v.y));
                fma2(msg[2 * j + 1], a1p, pk2(v.z, v.w));
            }
        }
    }

    float* outp = g_neigh + (size_t)dst[e] * OF;
#pragma unroll
    for (int o2 = 0; o2 < 8; o2++) {
        float a, b;
        upk2(msg[o2], a, b);
        atomicAdd(outp + 2 * o2, a);
        atomicAdd(outp + 2 * o2 + 1, b);
    }
}

// ---------------------------------------------------------------------------
// BN(training stats) + tanh + add neigh + relu + row L2 normalize
__global__ __launch_bounds__(256) void k_final(float* __restrict__ out,
                                               const float* __restrict__ gamma,
                                               const float* __restrict__ beta) {
    int n = blockIdx.x * 256 + threadIdx.x;
    if (n >= NN) return;
    const float inv = 1.0f / (float)NN;
    float z[OF];
    float ss = 0.0f;
#pragma unroll
    for (int o = 0; o < OF; o++) {
        float mu = g_stats[o] * inv;
        float var = g_stats[OF + o] * inv - mu * mu;
        float y = (g_y[(size_t)n * OF + o] - mu) * rsqrtf(var + BN_EPS);
        y = y * gamma[o] + beta[o];
        y = tanhf(y);
        float zz = y + g_neigh[(size_t)n * OF + o];
        zz = fmaxf(zz, 0.0f);
        z[o] = zz;
        ss += zz * zz;
    }
    float nrm = sqrtf(ss);
    float r = (nrm == 0.0f) ? 1.0f : (1.0f / nrm);
#pragma unroll
    for (int o = 0; o < OF; o++) out[(size_t)n * OF + o] = z[o] * r;
}

// ---------------------------------------------------------------------------
extern "C" void kernel_launch(void* const* d_in, const int* in_sizes, int n_in,
                              void* d_out, int out_size) {
    const float* h_neigh        = (const float*)d_in[0];
    const float* h_self         = (const float*)d_in[1];
    const float* edge_features  = (const float*)d_in[2];
    const int*   src            = (const int*)d_in[3];
    const int*   dst            = (const int*)d_in[4];
    const float* W_self         = (const float*)d_in[5];
    const float* bn_gamma       = (const float*)d_in[6];
    const float* bn_beta        = (const float*)d_in[7];
    const float* We1            = (const float*)d_in[8];
    const float* be1            = (const float*)d_in[9];
    const float* We2            = (const float*)d_in[10];
    const float* be2            = (const float*)d_in[11];
    float* out = (float*)d_out;

    const int smem_bytes = SMEM_FLOATS * 4;  // 70912 B
    cudaFuncSetAttribute(k_edge, cudaFuncAttributeMaxDynamicSharedMemorySize,
                         smem_bytes);

    k_zero<<<(NN * OF + 255) / 256, 256>>>();
    k_self<<<(NN + 255) / 256, 256>>>(h_self, W_self);
    k_edge<<<NE / 256, 256, smem_bytes>>>(edge_features, h_neigh, src, dst,
                                          We1, be1, We2, be2);
    k_final<<<(NN + 255) / 256, 256>>>(out, bn_gamma, bn_beta);
}